// round 5
// baseline (speedup 1.0000x reference)
#include <cuda_runtime.h>

// Problem constants: infer/ref shape (2,7,7,3,256,256) -> N=98 images, C=3, H=W=256
#define NIMG   98
#define HH     256
#define WW     256
#define ROWS_PER_BLK 32
#define TILES_PER_IMG (HH / ROWS_PER_BLK)   // 8
#define NBLOCKS (NIMG * TILES_PER_IMG)      // 784
#define CH_STRIDE (HH * WW)                 // 65536 floats per channel
#define IMG_STRIDE (3 * CH_STRIDE)          // per image

__device__ float g_partials[NBLOCKS];

__global__ __launch_bounds__(256, 4)
void detail_loss_main(const float* __restrict__ infer, const float* __restrict__ ref)
{
    __shared__ float tile[ROWS_PER_BLK + 2][WW];   // 34 x 256 floats = 34 KB
    __shared__ float red[256];

    const int tid = threadIdx.x;
    const int blk = blockIdx.x;
    const int n   = blk >> 3;        // image index
    const int t   = blk & 7;         // row-tile index
    const int h0  = t * ROWS_PER_BLK;

    const size_t base = (size_t)n * IMG_STRIDE;
    const float4* __restrict__ A = (const float4*)(infer + base);
    const float4* __restrict__ B = (const float4*)(ref   + base);
    const int CS4 = CH_STRIDE / 4;   // 16384 float4 per channel

    // ---- Load phase: build D = sum_c (infer - ref) for 34 rows x 256 cols ----
    // 34 rows * 64 float4-cols = 2176 units, 256 threads
    #pragma unroll 1
    for (int idx = tid; idx < (ROWS_PER_BLK + 2) * (WW / 4); idx += 256) {
        const int r  = idx >> 6;        // tile row 0..33
        const int c4 = idx & 63;        // float4 column
        const int gh = h0 - 1 + r;      // global row (may be -1 or 256 -> zero pad)
        float4 d = make_float4(0.f, 0.f, 0.f, 0.f);
        if ((unsigned)gh < (unsigned)HH) {
            const int off = gh * (WW / 4) + c4;
            float4 a0 = A[off];
            float4 b0 = B[off];
            float4 a1 = A[off + CS4];
            float4 b1 = B[off + CS4];
            float4 a2 = A[off + 2 * CS4];
            float4 b2 = B[off + 2 * CS4];
            d.x = (a0.x - b0.x) + (a1.x - b1.x) + (a2.x - b2.x);
            d.y = (a0.y - b0.y) + (a1.y - b1.y) + (a2.y - b2.y);
            d.z = (a0.z - b0.z) + (a1.z - b1.z) + (a2.z - b2.z);
            d.w = (a0.w - b0.w) + (a1.w - b1.w) + (a2.w - b2.w);
        }
        *(float4*)&tile[r][c4 * 4] = d;
    }
    __syncthreads();

    // ---- Compute phase: each thread owns one column, walks 32 interior rows ----
    const int w = tid;                     // 0..255
    const bool has_l = (w > 0);
    const bool has_r = (w < WW - 1);
    float acc = 0.f;
    #pragma unroll 8
    for (int r = 1; r <= ROWS_PER_BLK; r++) {
        const float dl = has_l ? tile[r][w - 1] : 0.f;
        const float dr = has_r ? tile[r][w + 1] : 0.f;
        const float du = tile[r - 1][w];
        const float dd = tile[r + 1][w];
        acc += fabsf(dr - dl) + fabsf(dd - du);
    }

    // ---- Block reduction ----
    red[tid] = acc;
    __syncthreads();
    #pragma unroll
    for (int s = 128; s > 0; s >>= 1) {
        if (tid < s) red[tid] += red[tid + s];
        __syncthreads();
    }
    if (tid == 0) g_partials[blk] = red[0];
}

__global__ __launch_bounds__(256)
void detail_loss_reduce(float* __restrict__ out)
{
    __shared__ float red[256];
    const int tid = threadIdx.x;
    float s = 0.f;
    for (int i = tid; i < NBLOCKS; i += 256) s += g_partials[i];
    red[tid] = s;
    __syncthreads();
    #pragma unroll
    for (int k = 128; k > 0; k >>= 1) {
        if (tid < k) red[tid] += red[tid + k];
        __syncthreads();
    }
    if (tid == 0) {
        // result = A / (4 * 98 * 258 * 256)  (0.5 grad coeff, /2 of the two losses,
        // mean denominators 98*258*256 for both terms)
        out[0] = red[0] * (1.0f / 25890816.0f);
    }
}

extern "C" void kernel_launch(void* const* d_in, const int* in_sizes, int n_in,
                              void* d_out, int out_size)
{
    const float* infer = (const float*)d_in[0];
    const float* ref   = (const float*)d_in[1];
    float* out = (float*)d_out;
    (void)in_sizes; (void)n_in; (void)out_size;

    detail_loss_main<<<NBLOCKS, 256>>>(infer, ref);
    detail_loss_reduce<<<1, 256>>>(out);
}